// round 16
// baseline (speedup 1.0000x reference)
#include <cuda_runtime.h>
#include <cstdint>

typedef unsigned long long ull;

#define NB 128
#define NT 4096
#define NTH 128
#define NCHUNK 16           // CTAs per batch — no co-residency needed (spin-free)
#define TOKC 256            // tokens per CTA (2 per thread)

__device__ float g_scratch[NB * NCHUNK * 18];   // [cta][sum, ctx16]
__device__ int   g_cnt[NB];                     // arrival counters (zero-init)

__constant__ ulonglong2 cW2q[32 * 4];   // W2 rows as 128-bit packed quads

__device__ __forceinline__ float ex2f_(float x) {
    float y; asm("ex2.approx.f32 %0, %1;" : "=f"(y) : "f"(x)); return y;
}
__device__ __forceinline__ float rcpf_(float x) {
    float y; asm("rcp.approx.f32 %0, %1;" : "=f"(y) : "f"(x)); return y;
}
__device__ __forceinline__ float tanhf_(float x) {
    float y; asm("tanh.approx.f32 %0, %1;" : "=f"(y) : "f"(x)); return y;
}
__device__ __forceinline__ void pfma(ull& d, ull a, ull b) {
    asm("fma.rn.f32x2 %0, %1, %2, %0;" : "+l"(d) : "l"(a), "l"(b));
}
__device__ __forceinline__ ull pack2(float a, float b) {
    ull p; asm("mov.b64 %0, {%1, %2};" : "=l"(p) : "f"(a), "f"(b)); return p;
}
__device__ __forceinline__ float2 unpack2(ull p) {
    float2 r; asm("mov.b64 {%0, %1}, %2;" : "=f"(r.x), "=f"(r.y) : "l"(p)); return r;
}
__device__ __forceinline__ int atom_add_acqrel(int* p, int v) {
    int old;
    asm volatile("atom.acq_rel.gpu.global.add.s32 %0, [%1], %2;"
                 : "=r"(old) : "l"(p), "r"(v) : "memory");
    return old;
}
__device__ __forceinline__ uint32_t s2u(const void* p) {
    uint32_t a;
    asm("{ .reg .u64 t; cvta.to.shared.u64 t, %1; cvt.u32.u64 %0, t; }"
        : "=r"(a) : "l"(p));
    return a;
}
__device__ __forceinline__ void cp16(uint32_t dst, const void* g) {
    asm volatile("cp.async.cg.shared.global [%0], [%1], 16;" :: "r"(dst), "l"(g));
}
__device__ __forceinline__ void cpcommit() {
    asm volatile("cp.async.commit_group;");
}
__device__ __forceinline__ void cpwait0() {
    asm volatile("cp.async.wait_group 0;");
}

// swizzled offset of (token, quarter) inside a 64-token x 64B tile buffer
__device__ __forceinline__ uint32_t qoff(int t, int q) {
    return (uint32_t)(t * 64 + ((q ^ ((t >> 1) & 3)) * 16));
}

__device__ __forceinline__ void stage_tile(uint32_t sw, const float* gsrc, int lane) {
    #pragma unroll
    for (int k = 0; k < 8; k++) {
        const int c = lane + k * 32;
        cp16(sw + qoff(c >> 2, c & 3), gsrc + (size_t)c * 4);
    }
    cpcommit();
}

// read one token's 16 floats (8 packed pairs) from the tile
__device__ __forceinline__ void read_tok(const char* buf, int t, ull* k) {
    #pragma unroll
    for (int q = 0; q < 4; q++) {
        ulonglong2 v = *reinterpret_cast<const ulonglong2*>(buf + qoff(t, q));
        k[2*q] = v.x; k[2*q+1] = v.y;
    }
}

__global__ void __launch_bounds__(NTH, 9)
attn_fused(const float* __restrict__ query,   // [B,1,16]
           const float* __restrict__ key,     // [B,T,16]
           const float* __restrict__ value,   // [B,T,16]
           const float* __restrict__ W1,      // [32,16]
           const float* __restrict__ bias,    // scalar
           const float* __restrict__ v_w,     // [1,32]
           const float* __restrict__ v_b,     // [1]
           float* __restrict__ out_ctx,       // [B,16]
           float* __restrict__ out_attn)      // [B,T]
{
    const int cta   = blockIdx.x;
    const int b     = cta >> 4;
    const int chunk = cta & 15;
    const int base  = chunk * TOKC;
    const int tid   = threadIdx.x;
    const int lane  = tid & 31;
    const int wid   = tid >> 5;

    __shared__ __align__(16) char swz[4][4096];   // per-warp staging buffers
    __shared__ ulonglong2 scv[32];   // .x=(qproj+bias, 0), .y lo = L*v_w[w]
    __shared__ float ssum[4];        // per-warp csum partials
    __shared__ float sred[4 * 16];   // ctx cross-warp reduction
    __shared__ float sbc[1];         // last-CTA: inv broadcast
    __shared__ int   slast;

    const uint32_t sw   = s2u(swz[wid]);
    const char*    bufc = swz[wid];

    const int tile = base + wid * 64;   // this warp's 64 tokens
    const float* krow = key   + (size_t)b * NT * 16;
    const float* vrow = value + (size_t)b * NT * 16;
    const float L = 1.4426950408889634f;

    // G1: key tile — issue immediately
    stage_tile(sw, krow + (size_t)tile * 16, lane);

    // q projection + v_w staging (W2 comes from __constant__)
    if (tid < 32) {
        const int w = tid;
        float acc = *bias;
        #pragma unroll
        for (int d = 0; d < 16; d++)
            acc = fmaf(query[b * 16 + d], W1[w * 16 + d], acc);
        scv[w].x = pack2(acc, 0.0f);
        scv[w].y = pack2(L * v_w[w], 0.0f);     // pre-scaled by log2(e)
    }
    __syncthreads();

    const float vbL = v_b[0] * L;

    // ---------- Scores + inline exp (no max pass: bounded scores) ----------
    cpwait0();
    __syncwarp();
    ull ka[8], kb[8];
    read_tok(bufc, lane,      ka);
    read_tok(bufc, lane + 32, kb);
    __syncwarp();
    stage_tile(sw, vrow + (size_t)tile * 16, lane);    // G2: value tile

    float a0 = vbL, a1 = vbL;
    #pragma unroll 4
    for (int w = 0; w < 32; w++) {
        const ulonglong2 cc = scv[w];          // one LDS.128: qproj pair + L*v_w
        ull acc0 = cc.x;
        ull acc1 = acc0;
        const float vwL = unpack2(cc.y).x;
        const ulonglong2* wr = &cW2q[w * 4];   // 128-bit constant loads
        ulonglong2 w01 = wr[0];
        pfma(acc0, ka[0], w01.x); pfma(acc1, kb[0], w01.x);
        pfma(acc0, ka[1], w01.y); pfma(acc1, kb[1], w01.y);
        ulonglong2 w23 = wr[1];
        pfma(acc0, ka[2], w23.x); pfma(acc1, kb[2], w23.x);
        pfma(acc0, ka[3], w23.y); pfma(acc1, kb[3], w23.y);
        ulonglong2 w45 = wr[2];
        pfma(acc0, ka[4], w45.x); pfma(acc1, kb[4], w45.x);
        pfma(acc0, ka[5], w45.y); pfma(acc1, kb[5], w45.y);
        ulonglong2 w67 = wr[3];
        pfma(acc0, ka[6], w67.x); pfma(acc1, kb[6], w67.x);
        pfma(acc0, ka[7], w67.y); pfma(acc1, kb[7], w67.y);

        const float2 h0 = unpack2(acc0);
        const float2 h1 = unpack2(acc1);
        const float t0h = tanhf_(h0.x + h0.y);
        const float t1h = tanhf_(h1.x + h1.y);
        a0 = fmaf(vwL, t0h, a0);
        a1 = fmaf(vwL, t1h, a1);
    }
    const float e0 = ex2f_(a0);        // exp(score), L pre-folded — bounded safe
    const float e1 = ex2f_(a1);

    // write unnormalized e; the batch's last CTA rescales in place
    float* ao = out_attn + (size_t)b * NT;
    ao[tile + lane]      = e0;
    ao[tile + lane + 32] = e1;

    // ---------- per-warp sum reduce ----------
    float csum = e0 + e1;
    #pragma unroll
    for (int o = 16; o > 0; o >>= 1)
        csum += __shfl_xor_sync(0xffffffffu, csum, o);
    if (lane == 0) ssum[wid] = csum;

    // ---------- Value accumulation (token-sequential: lower reg pressure) ----
    ull cv[8];
    #pragma unroll
    for (int i = 0; i < 8; i++) cv[i] = 0ull;

    cpwait0();
    __syncwarp();
    {
        ull va[8];
        read_tok(bufc, lane, va);
        const ull ee0 = pack2(e0, e0);
        #pragma unroll
        for (int i = 0; i < 8; i++) pfma(cv[i], ee0, va[i]);
    }
    {
        ull vb2[8];
        read_tok(bufc, lane + 32, vb2);
        const ull ee1 = pack2(e1, e1);
        #pragma unroll
        for (int i = 0; i < 8; i++) pfma(cv[i], ee1, vb2[i]);
    }

    float cvf[16];
    #pragma unroll
    for (int i = 0; i < 8; i++) {
        float2 u = unpack2(cv[i]);
        cvf[2*i] = u.x; cvf[2*i+1] = u.y;
    }

    // ---------- Deterministic ctx reduction over 4 warps ----------
    #pragma unroll
    for (int o = 16; o > 0; o >>= 1) {
        #pragma unroll
        for (int i = 0; i < 16; i++)
            cvf[i] += __shfl_xor_sync(0xffffffffu, cvf[i], o);
    }
    if (lane == 0) {
        #pragma unroll
        for (int i = 0; i < 16; i++) sred[wid * 16 + i] = cvf[i];
    }
    __syncthreads();
    if (tid == 0)
        g_scratch[cta * 18] = ssum[0] + ssum[1] + ssum[2] + ssum[3];
    if (tid < 16) {
        float a = sred[tid];
        #pragma unroll
        for (int w = 1; w < 4; w++) a += sred[w * 16 + tid];
        g_scratch[cta * 18 + 1 + tid] = a;   // ctx partial
    }
    __syncthreads();       // all scratch + attn writes done CTA-wide

    // ---------- Arrival; non-last CTAs EXIT (no spin anywhere) ----------
    if (tid == 0)
        slast = (atom_add_acqrel(&g_cnt[b], 1) == NCHUNK - 1);
    __syncthreads();
    if (!slast) return;

    // ---------- Last arriver: combine + rescale + ctx ----------
    if (tid == 0) {
        const float* gs = g_scratch + b * (NCHUNK * 18);
        float total = 0.0f;
        #pragma unroll
        for (int c = 0; c < NCHUNK; c++) total += gs[c * 18];   // fixed order
        sbc[0] = rcpf_(total);
    }
    __syncthreads();
    const float inv = sbc[0];

    if (tid < 16) {
        const float* gs = g_scratch + b * (NCHUNK * 18);
        float acc = 0.0f;
        #pragma unroll
        for (int c = 0; c < NCHUNK; c++) acc += gs[c * 18 + 1 + tid];
        out_ctx[b * 16 + tid] = acc * inv;
    }

    // rescale the batch's 4096 attn values (1024 float4, 8 per thread)
    float4* ap = reinterpret_cast<float4*>(ao);
    #pragma unroll
    for (int j = 0; j < 8; j++) {
        const int idx = tid + j * NTH;
        float4 v = ap[idx];
        v.x *= inv; v.y *= inv; v.z *= inv; v.w *= inv;
        ap[idx] = v;
    }

    // counter reset for graph replay (all arrivals already happened)
    if (tid == 0) g_cnt[b] = 0;
}

extern "C" void kernel_launch(void* const* d_in, const int* in_sizes, int n_in,
                              void* d_out, int out_size) {
    const float* query = (const float*)d_in[0];
    const float* key   = (const float*)d_in[1];
    const float* value = (const float*)d_in[2];
    const float* W1    = (const float*)d_in[3];
    const float* W2    = (const float*)d_in[4];
    const float* bias  = (const float*)d_in[5];
    const float* v_w   = (const float*)d_in[6];
    const float* v_b   = (const float*)d_in[7];

    float* out_ctx  = (float*)d_out;            // [B,1,16]
    float* out_attn = (float*)d_out + NB * 16;  // [B,T]

    cudaMemcpyToSymbolAsync(cW2q, W2, 32 * 16 * sizeof(float), 0,
                            cudaMemcpyDeviceToDevice);

    attn_fused<<<NB * NCHUNK, NTH>>>(query, key, value, W1,
                                     bias, v_w, v_b, out_ctx, out_attn);
}